// round 1
// baseline (speedup 1.0000x reference)
#include <cuda_runtime.h>
#include <math.h>

// ---------------------------------------------------------------------------
// get_model_pred: edge_embed = mlp2(pred_codes, We1,be1,We2,be2)
//                 type_pred  = mlp2(edge_embed, Wt1,bt1,Wt2,bt2)
//                 type_output= softmax(type_pred)
//                 types_w    = [1-p0, p1, p2, p3]  (shape 4 x E)
//                 multiW     = gate(types_w)
// Outputs concatenated: types_w(4E) | multiW(4E) | type_output(E*4) | edge(E*512)
// obj_codes (d_in[0]) is unused by the reference outputs.
// ---------------------------------------------------------------------------

#define D 512
#define BM 128
#define BN 128
#define BK 16
#define TM 8
#define TN 8

#define E_MAX 89700
// Scratch for the hidden layer h (E x 512). Static device global: allocation
// guards forbid cudaMalloc, __device__ arrays are the sanctioned workaround.
__device__ float g_h[(size_t)E_MAX * D];

__device__ __forceinline__ float gatef(float p) {
    const float BEL = 0.025f;
    const float HI  = 1.0f / 2.2f + 0.025f;   // 0.47954545...
    return (p <= BEL) ? 0.0f : ((p >= HI) ? 1.0f : 2.2f * (p - BEL));
}

// C = [relu](A @ B + bias), A: (E x 512) row-major, B: (512 x 512) row-major.
// Grid: (ceil(E/128), 4). 256 threads, 8x8 per-thread microtile.
template <bool RELU>
__global__ __launch_bounds__(256) void gemm512(
    const float* __restrict__ A, const float* __restrict__ B,
    const float* __restrict__ bias, float* __restrict__ C, int E)
{
    __shared__ float As[BK][BM];   // transposed A tile: As[k][row]
    __shared__ float Bs[BK][BN];   // Bs[k][col]

    const int tid = threadIdx.x;
    const int tx = tid & 15;          // 0..15 -> col group
    const int ty = tid >> 4;          // 0..15 -> row group
    const int rowBase = blockIdx.x * BM;
    const int colBase = blockIdx.y * BN;

    float acc[TM][TN];
#pragma unroll
    for (int i = 0; i < TM; i++)
#pragma unroll
        for (int j = 0; j < TN; j++) acc[i][j] = 0.0f;

    for (int kb = 0; kb < D; kb += BK) {
#pragma unroll
        for (int q = 0; q < 2; q++) {
            int s = q * 256 + tid;            // 0..511 float4 slots
            // A tile: 128 rows x 16 cols = 512 float4 (4 per row)
            {
                int r = s >> 2, k4 = (s & 3) << 2;
                float4 v = make_float4(0.f, 0.f, 0.f, 0.f);
                int gr = rowBase + r;
                if (gr < E)
                    v = *(const float4*)(A + (size_t)gr * D + kb + k4);
                As[k4 + 0][r] = v.x; As[k4 + 1][r] = v.y;
                As[k4 + 2][r] = v.z; As[k4 + 3][r] = v.w;
            }
            // B tile: 16 rows x 128 cols = 512 float4 (32 per row)
            {
                int k = s >> 5, c4 = (s & 31) << 2;
                *(float4*)&Bs[k][c4] =
                    *(const float4*)(B + (size_t)(kb + k) * D + colBase + c4);
            }
        }
        __syncthreads();

#pragma unroll
        for (int k = 0; k < BK; k++) {
            float a[TM], b[TN];
#pragma unroll
            for (int i = 0; i < TM; i++) a[i] = As[k][ty * TM + i];
#pragma unroll
            for (int j = 0; j < TN; j++) b[j] = Bs[k][tx * TN + j];
#pragma unroll
            for (int i = 0; i < TM; i++)
#pragma unroll
                for (int j = 0; j < TN; j++)
                    acc[i][j] = fmaf(a[i], b[j], acc[i][j]);
        }
        __syncthreads();
    }

    const int c0 = colBase + tx * TN;
#pragma unroll
    for (int i = 0; i < TM; i++) {
        int gr = rowBase + ty * TM + i;
        if (gr < E) {
#pragma unroll
            for (int j = 0; j < TN; j++) {
                float v = acc[i][j] + __ldg(&bias[c0 + j]);
                if (RELU) v = fmaxf(v, 0.0f);
                C[(size_t)gr * D + c0 + j] = v;
            }
        }
    }
}

// Head: per 128-row tile, T1 = relu(EE @ Wt1 + bt1)  (128 x 128, K=512),
// then t = T1 @ Wt2 + bt2 (4), softmax, stack/gate, write all small outputs.
__global__ __launch_bounds__(256) void head_kernel(
    const float* __restrict__ EE, const float* __restrict__ Wt1,
    const float* __restrict__ bt1, const float* __restrict__ Wt2,
    const float* __restrict__ bt2, float* __restrict__ out, int E)
{
    extern __shared__ float sm[];           // 128*129 floats (T1, padded); first
                                            // 16KB doubles as As/Bs during GEMM
    __shared__ float sWt2[D / 4 * 4];       // 128*4 = 512 floats
    __shared__ float sbt1[128];

    const int tid = threadIdx.x;
    const int tx = tid & 15;
    const int ty = tid >> 4;
    const int rowBase = blockIdx.x * BM;

    sWt2[tid]       = Wt2[tid];
    sWt2[tid + 256] = Wt2[tid + 256];
    if (tid < 128) sbt1[tid] = bt1[tid];

    float (*As)[BM] = (float (*)[BM])sm;          // [16][128]
    float (*Bs)[128] = (float (*)[128])(sm + BK * BM);

    float acc[TM][TN];
#pragma unroll
    for (int i = 0; i < TM; i++)
#pragma unroll
        for (int j = 0; j < TN; j++) acc[i][j] = 0.0f;

    for (int kb = 0; kb < D; kb += BK) {
#pragma unroll
        for (int q = 0; q < 2; q++) {
            int s = q * 256 + tid;
            {
                int r = s >> 2, k4 = (s & 3) << 2;
                float4 v = make_float4(0.f, 0.f, 0.f, 0.f);
                int gr = rowBase + r;
                if (gr < E)
                    v = *(const float4*)(EE + (size_t)gr * D + kb + k4);
                As[k4 + 0][r] = v.x; As[k4 + 1][r] = v.y;
                As[k4 + 2][r] = v.z; As[k4 + 3][r] = v.w;
            }
            {
                int k = s >> 5, c4 = (s & 31) << 2;   // Wt1: (512 x 128)
                *(float4*)&Bs[k][c4] =
                    *(const float4*)(Wt1 + (size_t)(kb + k) * 128 + c4);
            }
        }
        __syncthreads();
#pragma unroll
        for (int k = 0; k < BK; k++) {
            float a[TM], b[TN];
#pragma unroll
            for (int i = 0; i < TM; i++) a[i] = As[k][ty * TM + i];
#pragma unroll
            for (int j = 0; j < TN; j++) b[j] = Bs[k][tx * TN + j];
#pragma unroll
            for (int i = 0; i < TM; i++)
#pragma unroll
                for (int j = 0; j < TN; j++)
                    acc[i][j] = fmaf(a[i], b[j], acc[i][j]);
        }
        __syncthreads();
    }

    // Stage T1 = relu(acc + bt1) into padded SMEM (stride 129 -> conflict-free
    // column walks in phase 2).
    const int PAD = 129;
#pragma unroll
    for (int i = 0; i < TM; i++) {
        int r = ty * TM + i;
#pragma unroll
        for (int j = 0; j < TN; j++) {
            int c = tx * TN + j;
            sm[r * PAD + c] = fmaxf(acc[i][j] + sbt1[c], 0.0f);
        }
    }
    __syncthreads();

    // Phase 2: one thread per row -> 128x4 GEMV + softmax + gate + stores.
    if (tid < 128) {
        int gr = rowBase + tid;
        if (gr < E) {
            float t0 = __ldg(&bt2[0]), t1 = __ldg(&bt2[1]);
            float t2 = __ldg(&bt2[2]), t3 = __ldg(&bt2[3]);
            const float* row = sm + tid * PAD;
#pragma unroll 8
            for (int k = 0; k < 128; k++) {
                float x = row[k];
                t0 = fmaf(x, sWt2[k * 4 + 0], t0);
                t1 = fmaf(x, sWt2[k * 4 + 1], t1);
                t2 = fmaf(x, sWt2[k * 4 + 2], t2);
                t3 = fmaf(x, sWt2[k * 4 + 3], t3);
            }
            float m = fmaxf(fmaxf(t0, t1), fmaxf(t2, t3));
            float e0 = __expf(t0 - m), e1 = __expf(t1 - m);
            float e2 = __expf(t2 - m), e3 = __expf(t3 - m);
            float inv = 1.0f / (e0 + e1 + e2 + e3);
            float p0 = e0 * inv, p1 = e1 * inv, p2 = e2 * inv, p3 = e3 * inv;
            float tw0 = 1.0f - p0;

            size_t Es = (size_t)E;
            // types_w (4, E)
            out[0 * Es + gr] = tw0;
            out[1 * Es + gr] = p1;
            out[2 * Es + gr] = p2;
            out[3 * Es + gr] = p3;
            // multiW (4, E)
            float* mw = out + 4 * Es;
            mw[0 * Es + gr] = gatef(tw0);
            mw[1 * Es + gr] = gatef(p1);
            mw[2 * Es + gr] = gatef(p2);
            mw[3 * Es + gr] = gatef(p3);
            // type_output (E, 4)
            float* to = out + 8 * Es;
            to[(size_t)gr * 4 + 0] = p0;
            to[(size_t)gr * 4 + 1] = p1;
            to[(size_t)gr * 4 + 2] = p2;
            to[(size_t)gr * 4 + 3] = p3;
        }
    }
}

extern "C" void kernel_launch(void* const* d_in, const int* in_sizes, int n_in,
                              void* d_out, int out_size)
{
    // Inputs (metadata order): obj_codes, pred_codes, We1, be1, We2, be2,
    //                          Wt1, bt1, Wt2, bt2
    const float* pred = (const float*)d_in[1];
    const float* We1  = (const float*)d_in[2];
    const float* be1  = (const float*)d_in[3];
    const float* We2  = (const float*)d_in[4];
    const float* be2  = (const float*)d_in[5];
    const float* Wt1  = (const float*)d_in[6];
    const float* bt1  = (const float*)d_in[7];
    const float* Wt2  = (const float*)d_in[8];
    const float* bt2  = (const float*)d_in[9];

    const int E = in_sizes[1] / D;

    float* out  = (float*)d_out;
    float* edge = out + (size_t)12 * E;   // edge_embed region

    float* h = nullptr;
    cudaGetSymbolAddress((void**)&h, g_h);

    const int rb = (E + BM - 1) / BM;
    dim3 grid(rb, D / BN);

    gemm512<true ><<<grid, 256>>>(pred, We1, be1, h, E);
    gemm512<false><<<grid, 256>>>(h,    We2, be2, edge, E);

    const int head_smem = 128 * 129 * sizeof(float);   // 66048 B
    cudaFuncSetAttribute(head_kernel,
                         cudaFuncAttributeMaxDynamicSharedMemorySize, head_smem);
    head_kernel<<<rb, 256, head_smem>>>(edge, Wt1, bt1, Wt2, bt2, out, E);
}

// round 5
// speedup vs baseline: 3.7705x; 3.7705x over previous
#include <cuda_runtime.h>
#include <cstdint>
#include <math.h>

// ============================================================================
// get_model_pred — tf32 mma.sync (sm_80+ path; tcgen05 unavailable: harness
// ptxas targets plain sm_103, which rejects all 'a'-suffix features).
//   edge_embed = relu(pred@We1+b1)@We2+b2
//   head       = softmax(relu(edge@Wt1+bt1)@Wt2+bt2) ; stack ; gate
// Outputs: types_w(4,E) | multiW(4,E) | type_output(E,4) | edge_embed(E,512)
// ============================================================================

#define D 512
#define E_MAX 89700

// Hidden-layer scratch (cudaMalloc forbidden; __device__ global is sanctioned).
__device__ float g_h[(size_t)E_MAX * D];

// SMEM tile layout (floats):
//   As [128][36]  (pad 4  -> banks (4m+k)%32, all-distinct per fragment load)
//   Bs [32][136]  (pad 8  -> banks (8k+n)%32, all-distinct per fragment load)
#define AS_STRIDE 36
#define BS_STRIDE 136
#define AS_BYTES (128 * AS_STRIDE * 4)          // 18432
#define BS_BYTES (32 * BS_STRIDE * 4)           // 17408
#define STAGE_BYTES (AS_BYTES + BS_BYTES)       // 35840
#define NSTAGES 3
#define SMEM_TOTAL (NSTAGES * STAGE_BYTES)      // 107520

__device__ __forceinline__ uint32_t smem_u32(const void* p) {
    uint32_t a;
    asm("{ .reg .u64 t; cvta.to.shared.u64 t, %1; cvt.u32.u64 %0, t; }"
        : "=r"(a) : "l"(p));
    return a;
}
__device__ __forceinline__ uint32_t f2tf(float x) {   // round-to-nearest tf32
    uint32_t u;
    asm("cvt.rna.tf32.f32 %0, %1;" : "=r"(u) : "f"(x));
    return u;
}
__device__ __forceinline__ float gatef(float p) {
    const float BEL = 0.025f;
    const float HI  = 1.0f / 2.2f + 0.025f;
    return (p <= BEL) ? 0.0f : ((p >= HI) ? 1.0f : 2.2f * (p - BEL));
}
__device__ __forceinline__ void cpa16(uint32_t dst, const void* src, bool valid) {
    int sz = valid ? 16 : 0;   // src-size 0 => zero-fill 16B
    asm volatile("cp.async.cg.shared.global [%0], [%1], 16, %2;"
                 :: "r"(dst), "l"(src), "r"(sz) : "memory");
}
#define CP_COMMIT() asm volatile("cp.async.commit_group;" ::: "memory")
#define CP_WAIT(n)  asm volatile("cp.async.wait_group %0;" :: "n"(n) : "memory")

__device__ __forceinline__ void mma_tf32(float& d0, float& d1, float& d2, float& d3,
                                         uint32_t a0, uint32_t a1, uint32_t a2, uint32_t a3,
                                         uint32_t b0, uint32_t b1) {
    asm volatile(
        "mma.sync.aligned.m16n8k8.row.col.f32.tf32.tf32.f32 "
        "{%0,%1,%2,%3}, {%4,%5,%6,%7}, {%8,%9}, {%0,%1,%2,%3};"
        : "+f"(d0), "+f"(d1), "+f"(d2), "+f"(d3)
        : "r"(a0), "r"(a1), "r"(a2), "r"(a3), "r"(b0), "r"(b1));
}

// Issue one stage of cp.async loads. A: (E x D) row-major; B: (D x NW) row-major.
template <int NW>
__device__ __forceinline__ void load_tile(
    uint32_t sA, uint32_t sB, const float* __restrict__ Ag,
    const float* __restrict__ Bg, int rowBase, int colBase, int kb, int E, int tid)
{
#pragma unroll
    for (int i = 0; i < 4; i++) {                   // A: 1024 float4 slots
        int idx = i * 256 + tid;
        int row = idx >> 3, f4 = (idx & 7) << 2;
        bool v = (rowBase + row) < E;
        const float* src = Ag + (size_t)(rowBase + row) * D + kb + f4;
        cpa16(sA + (uint32_t)(row * AS_STRIDE + f4) * 4, v ? src : Ag, v);
    }
#pragma unroll
    for (int i = 0; i < 4; i++) {                   // B: 32 rows x 32 float4
        int idx = i * 256 + tid;
        int k = idx >> 5, f4 = (idx & 31) << 2;
        const float* src = Bg + (size_t)(kb + k) * NW + colBase + f4;
        cpa16(sB + (uint32_t)(k * BS_STRIDE + f4) * 4, src, true);
    }
}

// Warp-tile compute on one 32-deep K chunk.
__device__ __forceinline__ void compute_tile(
    const float* As, const float* Bs, float acc[4][4][4],
    int wm, int wn, int gid, int tig)
{
#pragma unroll
    for (int ks = 0; ks < 4; ks++) {
        const int k = ks * 8 + tig;
        uint32_t a[4][4], b[4][2];
#pragma unroll
        for (int mt = 0; mt < 4; mt++) {
            const int m = wm * 64 + mt * 16 + gid;
            a[mt][0] = f2tf(As[m * AS_STRIDE + k]);
            a[mt][1] = f2tf(As[(m + 8) * AS_STRIDE + k]);
            a[mt][2] = f2tf(As[m * AS_STRIDE + k + 4]);
            a[mt][3] = f2tf(As[(m + 8) * AS_STRIDE + k + 4]);
        }
#pragma unroll
        for (int nt = 0; nt < 4; nt++) {
            const int n = wn * 32 + nt * 8 + gid;
            b[nt][0] = f2tf(Bs[k * BS_STRIDE + n]);
            b[nt][1] = f2tf(Bs[(k + 4) * BS_STRIDE + n]);
        }
#pragma unroll
        for (int mt = 0; mt < 4; mt++)
#pragma unroll
            for (int nt = 0; nt < 4; nt++)
                mma_tf32(acc[mt][nt][0], acc[mt][nt][1], acc[mt][nt][2], acc[mt][nt][3],
                         a[mt][0], a[mt][1], a[mt][2], a[mt][3],
                         b[nt][0], b[nt][1]);
    }
}

// Shared pipelined mainloop: fills acc with A(rowBase:+128) @ B(:, colBase:+128).
template <int NW>
__device__ __forceinline__ void gemm_mainloop(
    char* smem, const float* __restrict__ Ag, const float* __restrict__ Bg,
    int rowBase, int colBase, int E, int tid, float acc[4][4][4],
    int wm, int wn, int gid, int tig)
{
    const uint32_t sb = smem_u32(smem);

#pragma unroll
    for (int mt = 0; mt < 4; mt++)
#pragma unroll
        for (int nt = 0; nt < 4; nt++)
#pragma unroll
            for (int r = 0; r < 4; r++) acc[mt][nt][r] = 0.0f;

    // prologue: stages 0,1
    load_tile<NW>(sb, sb + AS_BYTES, Ag, Bg, rowBase, colBase, 0, E, tid);
    CP_COMMIT();
    load_tile<NW>(sb + STAGE_BYTES, sb + STAGE_BYTES + AS_BYTES,
                  Ag, Bg, rowBase, colBase, 32, E, tid);
    CP_COMMIT();

    for (int kt = 0; kt < 16; kt++) {
        CP_WAIT(1);
        __syncthreads();
        if (kt + 2 < 16) {
            uint32_t st = sb + (uint32_t)((kt + 2) % NSTAGES) * STAGE_BYTES;
            load_tile<NW>(st, st + AS_BYTES, Ag, Bg, rowBase, colBase,
                          (kt + 2) * 32, E, tid);
        }
        CP_COMMIT();
        const float* As = (const float*)(smem + (kt % NSTAGES) * STAGE_BYTES);
        const float* Bs = As + 128 * AS_STRIDE;
        compute_tile(As, Bs, acc, wm, wn, gid, tig);
    }
    CP_WAIT(0);
    __syncthreads();
}

// ---------------------------------------------------------------------------
// Big GEMM: C(E x 512) = A @ B(512x512) + bias [, relu]. Grid (rb, 4).
// ---------------------------------------------------------------------------
template <bool RELU>
__global__ __launch_bounds__(256, 2) void gemm_mma(
    const float* __restrict__ Ag, const float* __restrict__ Bg,
    const float* __restrict__ bias, float* __restrict__ C, int E)
{
    extern __shared__ __align__(16) char smem[];
    __shared__ float sbias[128];

    const int tid = threadIdx.x;
    const int wid = tid >> 5, lane = tid & 31;
    const int wm = wid >> 2, wn = wid & 3;       // 2 x 4 warp grid
    const int gid = lane >> 2, tig = lane & 3;
    const int rowBase = blockIdx.x * 128;
    const int colBase = blockIdx.y * 128;

    if (tid < 128) sbias[tid] = bias[colBase + tid];

    float acc[4][4][4];
    gemm_mainloop<D>(smem, Ag, Bg, rowBase, colBase, E, tid, acc, wm, wn, gid, tig);

#pragma unroll
    for (int mt = 0; mt < 4; mt++) {
        const int r0 = rowBase + wm * 64 + mt * 16 + gid;
#pragma unroll
        for (int nt = 0; nt < 4; nt++) {
            const int cl = wn * 32 + nt * 8 + tig * 2;
            const int c = colBase + cl;
            float v0 = acc[mt][nt][0] + sbias[cl];
            float v1 = acc[mt][nt][1] + sbias[cl + 1];
            float v2 = acc[mt][nt][2] + sbias[cl];
            float v3 = acc[mt][nt][3] + sbias[cl + 1];
            if (RELU) {
                v0 = fmaxf(v0, 0.f); v1 = fmaxf(v1, 0.f);
                v2 = fmaxf(v2, 0.f); v3 = fmaxf(v3, 0.f);
            }
            if (r0 < E)     *(float2*)&C[(size_t)r0 * D + c]       = make_float2(v0, v1);
            if (r0 + 8 < E) *(float2*)&C[(size_t)(r0 + 8) * D + c] = make_float2(v2, v3);
        }
    }
}

// ---------------------------------------------------------------------------
// Head: T1 = relu(edge @ Wt1 + bt1) (128x128, K=512) via mma, then per-row
// 128->4 GEMV + softmax + stack + gate + all small outputs. Grid (rb).
// ---------------------------------------------------------------------------
__global__ __launch_bounds__(256, 2) void head_mma(
    const float* __restrict__ EE, const float* __restrict__ Wt1,
    const float* __restrict__ bt1, const float* __restrict__ Wt2,
    const float* __restrict__ bt2, float* __restrict__ out, int E)
{
    extern __shared__ __align__(16) char smem[];
    __shared__ float sWt2[512];
    __shared__ float sbt1[128];

    const int tid = threadIdx.x;
    const int wid = tid >> 5, lane = tid & 31;
    const int wm = wid >> 2, wn = wid & 3;
    const int gid = lane >> 2, tig = lane & 3;
    const int rowBase = blockIdx.x * 128;

    if (tid < 128) {
        sbt1[tid] = bt1[tid];
        sWt2[tid]       = Wt2[tid];
        sWt2[tid + 128] = Wt2[tid + 128];
        sWt2[tid + 256] = Wt2[tid + 256];
        sWt2[tid + 384] = Wt2[tid + 384];
    }

    float acc[4][4][4];
    gemm_mainloop<128>(smem, EE, Wt1, rowBase, 0, E, tid, acc, wm, wn, gid, tig);

    // T1 -> padded slab [128][129] (reuses pipeline smem; safe after CP_WAIT(0)+sync)
    float* T1 = (float*)smem;
#pragma unroll
    for (int mt = 0; mt < 4; mt++) {
        const int r = wm * 64 + mt * 16 + gid;
#pragma unroll
        for (int nt = 0; nt < 4; nt++) {
            const int c = wn * 32 + nt * 8 + tig * 2;
            T1[r * 129 + c]           = fmaxf(acc[mt][nt][0] + sbt1[c], 0.f);
            T1[r * 129 + c + 1]       = fmaxf(acc[mt][nt][1] + sbt1[c + 1], 0.f);
            T1[(r + 8) * 129 + c]     = fmaxf(acc[mt][nt][2] + sbt1[c], 0.f);
            T1[(r + 8) * 129 + c + 1] = fmaxf(acc[mt][nt][3] + sbt1[c + 1], 0.f);
        }
    }
    __syncthreads();

    // Phase 2: one thread per row
    if (tid < 128) {
        const int gr = rowBase + tid;
        if (gr < E) {
            float t0 = __ldg(&bt2[0]), t1 = __ldg(&bt2[1]);
            float t2 = __ldg(&bt2[2]), t3 = __ldg(&bt2[3]);
            const float* rp = T1 + tid * 129;
#pragma unroll 8
            for (int k = 0; k < 128; k++) {
                float x = rp[k];
                t0 = fmaf(x, sWt2[k * 4 + 0], t0);
                t1 = fmaf(x, sWt2[k * 4 + 1], t1);
                t2 = fmaf(x, sWt2[k * 4 + 2], t2);
                t3 = fmaf(x, sWt2[k * 4 + 3], t3);
            }
            float m = fmaxf(fmaxf(t0, t1), fmaxf(t2, t3));
            float e0 = __expf(t0 - m), e1 = __expf(t1 - m);
            float e2 = __expf(t2 - m), e3 = __expf(t3 - m);
            float inv = 1.0f / (e0 + e1 + e2 + e3);
            float p0 = e0 * inv, p1 = e1 * inv, p2 = e2 * inv, p3 = e3 * inv;
            float tw0 = 1.0f - p0;

            const size_t Es = (size_t)E;
            out[0 * Es + gr] = tw0;
            out[1 * Es + gr] = p1;
            out[2 * Es + gr] = p2;
            out[3 * Es + gr] = p3;
            float* mw = out + 4 * Es;
            mw[0 * Es + gr] = gatef(tw0);
            mw[1 * Es + gr] = gatef(p1);
            mw[2 * Es + gr] = gatef(p2);
            mw[3 * Es + gr] = gatef(p3);
            float* to = out + 8 * Es;
            to[(size_t)gr * 4 + 0] = p0;
            to[(size_t)gr * 4 + 1] = p1;
            to[(size_t)gr * 4 + 2] = p2;
            to[(size_t)gr * 4 + 3] = p3;
        }
    }
}

// ---------------------------------------------------------------------------
extern "C" void kernel_launch(void* const* d_in, const int* in_sizes, int n_in,
                              void* d_out, int out_size)
{
    const float* pred = (const float*)d_in[1];
    const float* We1  = (const float*)d_in[2];
    const float* be1  = (const float*)d_in[3];
    const float* We2  = (const float*)d_in[4];
    const float* be2  = (const float*)d_in[5];
    const float* Wt1  = (const float*)d_in[6];
    const float* bt1  = (const float*)d_in[7];
    const float* Wt2  = (const float*)d_in[8];
    const float* bt2  = (const float*)d_in[9];

    const int E = in_sizes[1] / D;
    float* out  = (float*)d_out;
    float* edge = out + (size_t)12 * E;

    float* h = nullptr;
    cudaGetSymbolAddress((void**)&h, g_h);

    cudaFuncSetAttribute(gemm_mma<true>,
                         cudaFuncAttributeMaxDynamicSharedMemorySize, SMEM_TOTAL);
    cudaFuncSetAttribute(gemm_mma<false>,
                         cudaFuncAttributeMaxDynamicSharedMemorySize, SMEM_TOTAL);
    cudaFuncSetAttribute(head_mma,
                         cudaFuncAttributeMaxDynamicSharedMemorySize, SMEM_TOTAL);

    const int rb = (E + 127) / 128;
    dim3 grid(rb, 4);

    gemm_mma<true ><<<grid, 256, SMEM_TOTAL>>>(pred, We1, be1, h, E);
    gemm_mma<false><<<grid, 256, SMEM_TOTAL>>>(h,    We2, be2, edge, E);
    head_mma<<<rb, 256, SMEM_TOTAL>>>(edge, Wt1, bt1, Wt2, bt2, out, E);
}